// round 11
// baseline (speedup 1.0000x reference)
#include <cuda_runtime.h>
#include <cuda_bf16.h>
#include <cstdint>
#include <math.h>

// Problem constants
#define LSEQ   4096
#define DEMB   256
#define HID    256          // per-direction hidden
#define G4H    1024         // 4*HID
#define NT     24
#define START_TAG 22
#define STOP_TAG  23
#define NEGINF (-1.0e6f)

// ---------------- scratch (device globals; no allocation allowed) ----------------
__device__ float g_xp[2][LSEQ * G4H];      // input projections per direction (scan order)
__device__ float g_lstm_out[LSEQ * 512];   // [t][0:256)=fwd h, [256:512)=bwd h (final order)
__device__ float g_feats[LSEQ * NT];

// ---------------- helpers ----------------
__device__ __forceinline__ uint32_t s2u(const void* p) {
    return (uint32_t)__cvta_generic_to_shared(p);
}
__device__ __forceinline__ void cluster_sync_() {
    asm volatile("barrier.cluster.arrive.aligned;" ::: "memory");
    asm volatile("barrier.cluster.wait.aligned;" ::: "memory");
}
__device__ __forceinline__ void mbar_init(uint32_t a, uint32_t cnt) {
    asm volatile("mbarrier.init.shared.b64 [%0], %1;" :: "r"(a), "r"(cnt) : "memory");
}
__device__ __forceinline__ void mbar_expect_tx(uint32_t a, uint32_t bytes) {
    asm volatile("mbarrier.arrive.expect_tx.shared.b64 _, [%0], %1;"
                 :: "r"(a), "r"(bytes) : "memory");
}
__device__ __forceinline__ void mbar_wait(uint32_t a, uint32_t parity) {
    asm volatile(
        "{\n\t"
        ".reg .pred P1;\n"
        "LW_%=:\n\t"
        "mbarrier.try_wait.parity.acquire.cta.shared::cta.b64 P1, [%0], %1, 0x989680;\n\t"
        "@P1 bra LD_%=;\n\t"
        "bra LW_%=;\n"
        "LD_%=:\n\t"
        "}"
        :: "r"(a), "r"(parity) : "memory");
}
__device__ __forceinline__ uint32_t mapa_(uint32_t a, uint32_t pc) {
    uint32_t r;
    asm("mapa.shared::cluster.u32 %0, %1, %2;" : "=r"(r) : "r"(a), "r"(pc));
    return r;
}
__device__ __forceinline__ void st_async_tx(uint32_t raddr, float v, uint32_t rbar) {
    asm volatile("st.async.shared::cluster.mbarrier::complete_tx::bytes.b32 [%0], %1, [%2];"
                 :: "r"(raddr), "r"(__float_as_uint(v)), "r"(rbar) : "memory");
}
// 128-byte bulk copy: local SMEM -> peer SMEM, one tx completion on peer's mbarrier
__device__ __forceinline__ void bulk_s2c_128(uint32_t dst, uint32_t src, uint32_t rbar) {
    asm volatile("cp.async.bulk.shared::cluster.shared::cta.mbarrier::complete_tx::bytes "
                 "[%0], [%1], 128, [%2];"
                 :: "r"(dst), "r"(src), "r"(rbar) : "memory");
}
__device__ __forceinline__ void fence_async_() {
    asm volatile("fence.proxy.async.shared::cta;" ::: "memory");
}
// fast, branch-free activations (__expf saturates cleanly at +-inf)
__device__ __forceinline__ float fsig(float x) {
    return __fdividef(1.0f, 1.0f + __expf(-x));
}
__device__ __forceinline__ float ftanh_(float x) {
    return 1.0f - __fdividef(2.0f, __expf(2.0f * x) + 1.0f);
}

// ---------------- kernel 1: embedding gather + input projection ----------------
__global__ __launch_bounds__(1024, 1)
void proj_kernel(const int* __restrict__ sent, const float* __restrict__ emb,
                 const float* __restrict__ Wf, const float* __restrict__ bihf,
                 const float* __restrict__ bhhf,
                 const float* __restrict__ Wb, const float* __restrict__ bihb,
                 const float* __restrict__ bhhb)
{
    __shared__ float4 xs[8][64];     // 8 timesteps x 256 floats
    const int dir = blockIdx.y;
    const int t0  = blockIdx.x * 8;
    const int tid = threadIdx.x;

    if (tid < 512) {
        int tt = tid >> 6, k4 = tid & 63;
        int s  = t0 + tt;
        int tok = sent[dir ? (LSEQ - 1 - s) : s];
        xs[tt][k4] = ((const float4*)emb)[(size_t)tok * 64 + k4];
    }
    __syncthreads();

    const float* W = dir ? Wb : Wf;
    const int row = tid;
    const float bias = dir ? (bihb[row] + bhhb[row]) : (bihf[row] + bhhf[row]);
    float acc[8];
#pragma unroll
    for (int i = 0; i < 8; i++) acc[i] = bias;

    const float4* W4 = (const float4*)(W + (size_t)row * DEMB);
#pragma unroll 8
    for (int k4 = 0; k4 < 64; k4++) {
        float4 w4 = __ldg(&W4[k4]);
#pragma unroll
        for (int tt = 0; tt < 8; tt++) {
            float4 x4 = xs[tt][k4];
            acc[tt] += w4.x * x4.x + w4.y * x4.y + w4.z * x4.z + w4.w * x4.w;
        }
    }
    float* out = g_xp[dir];
#pragma unroll
    for (int tt = 0; tt < 8; tt++)
        out[(size_t)(t0 + tt) * G4H + row] = acc[tt];
}

// ---------------- kernel 2: the sequential LSTM recurrence ----------------
// Grid: 16 CTAs, cluster of 8. Cluster 0 = forward, cluster 1 = backward.
// Each CTA owns h-slice [rank*32, rank*32+32).
// Thread layout: lrow = tid>>2 (local gate row, 0..127), ks = tid&3 (K-quarter).
// Each thread: 1 gate row x 64 K in registers (32 f32x2 pairs). Quad shfl-reduce
// over ks -> 128 leader STS -> one bar -> tail warp reads 4 LDS per lane.
// h broadcast: tail stages 128B in SMEM, 8 lanes each issue ONE cp.async.bulk
// (128B) to one peer -> 8 tx-arrivals per phase barrier instead of 256.
//
// RE-ARM ORDERING (proven in R10): full[p] is re-armed by tid0 IMMEDIATELY after
// its wait completes — before this CTA's __syncthreads, hence before any of this
// CTA's step-t sends. A peer's step-(t+1) tx into our full[p] requires that peer
// to pass full[p^1] at t+1, which requires OUR step-t sends, which follow our
// __syncthreads, which tid0 only reaches after re-arming.
__global__ __launch_bounds__(512, 1) __cluster_dims__(8, 1, 1)
void lstm_kernel(const float* __restrict__ h0, const float* __restrict__ c0,
                 const float* __restrict__ Whh_f, const float* __restrict__ Whh_b)
{
    __shared__ __align__(16) float hb[2][HID];
    __shared__ float part[2][128];
    __shared__ __align__(16) float stg[2][32];
    __shared__ __align__(8) unsigned long long mb_full[2];

    const int tid = threadIdx.x;
    uint32_t rank;
    asm("mov.u32 %0, %%cluster_ctarank;" : "=r"(rank));
    const int dir = blockIdx.x >> 3;

    const float* Whh = dir ? Whh_b : Whh_f;
    const float* xp  = g_xp[dir];

    const int lrow = tid >> 2;          // 0..127 : local gate row (g*32 + j)
    const int ks   = tid & 3;           // K quarter
    const int g    = lrow >> 5;
    const int j    = lrow & 31;
    const int grow = g * 256 + (int)rank * 32 + j;   // global gate row
    const int k0   = ks * 64;

    // W_hh: 64 K-values per thread as 32 packed f32x2 (row 1024B-aligned, k0*4 256B-aligned)
    unsigned long long w2[32];
    const unsigned long long* wrow =
        (const unsigned long long*)(Whh + (size_t)grow * HID + k0);
#pragma unroll
    for (int kk = 0; kk < 32; kk++) w2[kk] = __ldg(&wrow[kk]);

    const uint32_t fb0 = s2u(&mb_full[0]);
    const uint32_t fb1 = s2u(&mb_full[1]);

    // precomputed remote addresses for the bulk broadcast (lanes 0..7 of warp0)
    uint32_t dstA = 0, dstB = 0, barA = 0, barB = 0;
    if (tid < 8) {
        dstA = mapa_(s2u(&hb[1][rank * 32]), (uint32_t)tid);  // p==0 writes hb[1]
        dstB = mapa_(s2u(&hb[0][rank * 32]), (uint32_t)tid);  // p==1 writes hb[0]
        barA = mapa_(fb1, (uint32_t)tid);
        barB = mapa_(fb0, (uint32_t)tid);
    }
    const uint32_t stg0 = s2u(&stg[0][0]);
    const uint32_t stg1 = s2u(&stg[1][0]);

    // init + arm BEFORE cluster_sync so no tx can hit an un-armed barrier
    if (tid == 0) {
        mbar_init(fb0, 1);
        mbar_init(fb1, 1);
        mbar_expect_tx(fb0, 1024);   // phase 0: h0 fill
        mbar_expect_tx(fb1, 1024);   // phase 0: t=0 producer fill
    }
    __syncthreads();
    cluster_sync_();

    float c = 0.0f;
    float xpv[4] = {0.f, 0.f, 0.f, 0.f};
    if (tid < 32) {
        c = c0[dir * HID + rank * 32 + tid];
        float h0v = h0[dir * HID + rank * 32 + tid];
#pragma unroll
        for (int gg = 0; gg < 4; gg++)
            xpv[gg] = xp[gg * 256 + rank * 32 + tid];
        // one-time h0 broadcast via st.async (tx -> full[0]; 1024B total per barrier)
        uint32_t lslot = s2u(&hb[0][rank * 32 + tid]);
#pragma unroll
        for (int pc = 0; pc < 8; pc++)
            st_async_tx(mapa_(lslot, pc), h0v, mapa_(fb0, pc));
    }

    uint32_t phF0 = 0, phF1 = 0;
    int p = 0;
    for (int t = 0; t < LSEQ; t++) {
        // wait h(t) in hb[p], then re-arm the SAME barrier (safe: see note above)
        if (p == 0) {
            mbar_wait(fb0, phF0); phF0 ^= 1;
            if (tid == 0) mbar_expect_tx(fb0, 1024);
        } else {
            mbar_wait(fb1, phF1); phF1 ^= 1;
            if (tid == 0) mbar_expect_tx(fb1, 1024);
        }

        // prefetch next step's xp rows (consumed one full step later)
        float xpn[4] = {0.f, 0.f, 0.f, 0.f};
        if (tid < 32 && t + 1 < LSEQ) {
#pragma unroll
            for (int gg = 0; gg < 4; gg++)
                xpn[gg] = __ldg(&xp[(size_t)(t + 1) * G4H + gg * 256 + rank * 32 + tid]);
        }

        // 64-wide K-quarter dot via packed f32x2 FMA (8-lane broadcast LDS.128)
        const ulonglong2* h8 = (const ulonglong2*)&hb[p][k0];
        unsigned long long a0 = 0ull, a1 = 0ull;
#pragma unroll
        for (int q = 0; q < 16; q++) {
            ulonglong2 hv = h8[q];
            asm("fma.rn.f32x2 %0, %1, %2, %0;" : "+l"(a0) : "l"(w2[2 * q]),     "l"(hv.x));
            asm("fma.rn.f32x2 %0, %1, %2, %0;" : "+l"(a1) : "l"(w2[2 * q + 1]), "l"(hv.y));
        }
        asm("add.rn.f32x2 %0, %1, %2;" : "=l"(a0) : "l"(a0), "l"(a1));
        uint32_t alo, ahi;
        asm("mov.b64 {%0,%1}, %2;" : "=r"(alo), "=r"(ahi) : "l"(a0));
        float s = __uint_as_float(alo) + __uint_as_float(ahi);
        // reduce over the 4 K-quarters (quad-local shfl)
        s += __shfl_down_sync(0xffffffffu, s, 2);
        s += __shfl_down_sync(0xffffffffu, s, 1);
        if (ks == 0) part[p][lrow] = s;
        __syncthreads();      // part[p] ready; all local reads of hb[p] retired

        if (tid < 32) {
            const int jj = tid;
            float gv0 = xpv[0] + part[p][jj];
            float gv1 = xpv[1] + part[p][32 + jj];
            float gv2 = xpv[2] + part[p][64 + jj];
            float gv3 = xpv[3] + part[p][96 + jj];

            float ii  = fsig(gv0);
            float ff  = fsig(gv1);
            float ggt = ftanh_(gv2);
            float oo  = fsig(gv3);
            c = ff * c + ii * ggt;
            float hj = oo * ftanh_(c);

            // emit to gmem in FINAL time order (backward direction un-reverses here)
            int tt = dir ? (LSEQ - 1 - t) : t;
            g_lstm_out[(size_t)tt * 512 + dir * 256 + rank * 32 + jj] = hj;

            if (t + 1 < LSEQ) {
                stg[p][jj] = hj;               // stage 128B
                __syncwarp();
                fence_async_();                // order STS before async-proxy bulk read
                if (tid < 8) {
                    uint32_t dst = (p == 0) ? dstA : dstB;
                    uint32_t bar = (p == 0) ? barA : barB;
                    uint32_t src = (p == 0) ? stg0 : stg1;
                    bulk_s2c_128(dst, src, bar);   // 1 tx (128B) per peer
                }
            }
#pragma unroll
            for (int gg = 0; gg < 4; gg++) xpv[gg] = xpn[gg];
        }
        // no second __syncthreads: part and stg are double-buffered by p; reuse at
        // t+2 is ordered through two full-barrier generations (every CTA's t+2
        // fill requires our step-(t+1) sends, which follow our step-(t+1)
        // __syncthreads, which follows this step's part[p]/stg[p] reads).
        p ^= 1;
    }
}

// ---------------- kernel 3: feats = lstm_out @ W_out^T + b_out ----------------
__global__ __launch_bounds__(256, 4)
void feats_kernel(const float* __restrict__ Wout, const float* __restrict__ bout)
{
    int gw   = (blockIdx.x * blockDim.x + threadIdx.x) >> 5;
    int lane = threadIdx.x & 31;
    if (gw >= LSEQ * NT) return;
    int t = gw / NT, n = gw % NT;

    const float4* xr = (const float4*)(g_lstm_out + (size_t)t * 512);
    const float4* wr = (const float4*)(Wout + (size_t)n * 512);
    float acc = 0.0f;
#pragma unroll
    for (int q = 0; q < 4; q++) {
        float4 a = xr[q * 32 + lane];
        float4 b = __ldg(&wr[q * 32 + lane]);
        acc += a.x * b.x + a.y * b.y + a.z * b.z + a.w * b.w;
    }
#pragma unroll
    for (int off = 16; off; off >>= 1)
        acc += __shfl_down_sync(0xffffffffu, acc, off);
    if (lane == 0) g_feats[t * NT + n] = acc + bout[n];
}

// ---------------- kernel 4: Viterbi forward + backtrace ----------------
// Critical recurrence: shfl + add + 5-deep FMNMX tree + add (value only).
// Argmax recovered OFF the critical path via exact equality mask: m is one of
// the sc[k] values (pure fmaxf, no arithmetic), lowest set bit == jnp.argmax
// first-index semantics. bp kept in SMEM for an LDS backtrace.
#define BP_BYTES   (LSEQ * NT)               // 98304
#define FCH_BYTES  (256 * NT * 4)            // 24576
#define PATH_BYTES (LSEQ * 4)                // 16384
#define VSMEM      (BP_BYTES + FCH_BYTES + PATH_BYTES + 128)

__device__ __forceinline__ float vmax24_(const float* sc) {
    float v12[12];
#pragma unroll
    for (int m = 0; m < 12; m++) v12[m] = fmaxf(sc[2 * m], sc[2 * m + 1]);
    float v6[6];
#pragma unroll
    for (int m = 0; m < 6; m++) v6[m] = fmaxf(v12[2 * m], v12[2 * m + 1]);
    float v3[3];
#pragma unroll
    for (int m = 0; m < 3; m++) v3[m] = fmaxf(v6[2 * m], v6[2 * m + 1]);
    return fmaxf(fmaxf(v3[0], v3[1]), v3[2]);
}
__device__ __forceinline__ int argeq24_(const float* sc, float m) {
    unsigned msk = 0u;
#pragma unroll
    for (int k = 0; k < NT; k++) msk |= (sc[k] == m) ? (1u << k) : 0u;
    return __ffs(msk) - 1;
}

__global__ void viterbi_kernel(const float* __restrict__ trans,
                               float* __restrict__ out, int out_size)
{
    extern __shared__ char sm[];
    unsigned char* bp   = (unsigned char*)sm;
    float*         fch  = (float*)(sm + BP_BYTES);
    int*           path = (int*)(sm + BP_BYTES + FCH_BYTES);
    __shared__ float score_s;

    const int tid = threadIdx.x;

    float fvr = (tid == START_TAG) ? 0.0f : NEGINF;
    float trow[NT];
    if (tid < NT) {
#pragma unroll
        for (int p_ = 0; p_ < NT; p_++) trow[p_] = trans[tid * NT + p_];
    } else {
#pragma unroll
        for (int p_ = 0; p_ < NT; p_++) trow[p_] = 0.0f;
    }
    __syncthreads();

    for (int ch = 0; ch < LSEQ / 256; ch++) {
        const float* src = g_feats + (size_t)ch * 256 * NT;
        for (int i = tid; i < 256 * NT; i += blockDim.x) fch[i] = src[i];
        __syncthreads();

        if (tid < 32) {
            for (int s = 0; s < 256; s++) {
                int t = ch * 256 + s;
                float sc[NT];
#pragma unroll
                for (int k = 0; k < NT; k++)
                    sc[k] = __shfl_sync(0xffffffffu, fvr, k) + trow[k];

                float m = vmax24_(sc);                    // short critical chain
                float fval = (tid < NT) ? fch[s * NT + tid] : 0.0f;
                fvr = m + fval;                           // recurrence closed

                int bi = argeq24_(sc, m);                 // off critical path
                if (tid < NT) bp[t * NT + tid] = (unsigned char)bi;
            }
        }
        __syncthreads();
    }

    if (tid < 32) {
        float sc[NT];
#pragma unroll
        for (int k = 0; k < NT; k++)
            sc[k] = __shfl_sync(0xffffffffu, fvr, k) + __ldg(&trans[STOP_TAG * NT + k]);
        float m = vmax24_(sc);
        int bi = argeq24_(sc, m);

        if (tid == 0) {
            score_s = m;
            int tag = bi;
            for (int t = LSEQ - 1; t >= 0; t--) {
                path[t] = tag;
                tag = bp[t * NT + tag];
            }
        }
    }
    __syncthreads();

    // output: tuple (path_score, best_path) flattened as float32
    if (out_size >= LSEQ + 1) {
        if (tid == 0) out[0] = score_s;
        for (int t = tid; t < LSEQ; t += blockDim.x) out[1 + t] = (float)path[t];
    } else if (out_size >= LSEQ) {
        for (int t = tid; t < LSEQ; t += blockDim.x) out[t] = (float)path[t];
    } else if (out_size >= 1) {
        if (tid == 0) out[0] = score_s;
    }
}

// ---------------- launch ----------------
extern "C" void kernel_launch(void* const* d_in, const int* in_sizes, int n_in,
                              void* d_out, int out_size)
{
    const int*   sent  = (const int*)d_in[0];
    const float* h0    = (const float*)d_in[1];
    const float* c0    = (const float*)d_in[2];
    const float* emb   = (const float*)d_in[3];
    const float* Wihf  = (const float*)d_in[4];
    const float* Whhf  = (const float*)d_in[5];
    const float* bihf  = (const float*)d_in[6];
    const float* bhhf  = (const float*)d_in[7];
    const float* Wihb  = (const float*)d_in[8];
    const float* Whhb  = (const float*)d_in[9];
    const float* bihb  = (const float*)d_in[10];
    const float* bhhb  = (const float*)d_in[11];
    const float* Wout  = (const float*)d_in[12];
    const float* bout  = (const float*)d_in[13];
    const float* trans = (const float*)d_in[14];

    cudaFuncSetAttribute(viterbi_kernel,
                         cudaFuncAttributeMaxDynamicSharedMemorySize, VSMEM);

    proj_kernel<<<dim3(LSEQ / 8, 2), 1024>>>(sent, emb, Wihf, bihf, bhhf,
                                             Wihb, bihb, bhhb);
    lstm_kernel<<<16, 512>>>(h0, c0, Whhf, Whhb);

    int nwarps  = LSEQ * NT;
    int nblocks = (nwarps * 32 + 255) / 256;
    feats_kernel<<<nblocks, 256>>>(Wout, bout);

    viterbi_kernel<<<1, 128, VSMEM>>>(trans, (float*)d_out, out_size);
}

// round 13
// speedup vs baseline: 2.6350x; 2.6350x over previous
#include <cuda_runtime.h>
#include <cuda_bf16.h>
#include <cstdint>
#include <math.h>

// Problem constants
#define LSEQ   4096
#define DEMB   256
#define HID    256          // per-direction hidden
#define G4H    1024         // 4*HID
#define NT     24
#define START_TAG 22
#define STOP_TAG  23
#define NEGINF (-1.0e6f)

// ---------------- scratch (device globals; no allocation allowed) ----------------
__device__ float g_xp[2][LSEQ * G4H];      // input projections per direction (scan order)
__device__ float g_lstm_out[LSEQ * 512];   // [t][0:256)=fwd h, [256:512)=bwd h (final order)
__device__ float g_feats[LSEQ * NT];

// ---------------- helpers ----------------
__device__ __forceinline__ uint32_t s2u(const void* p) {
    return (uint32_t)__cvta_generic_to_shared(p);
}
__device__ __forceinline__ void cluster_sync_() {
    asm volatile("barrier.cluster.arrive.aligned;" ::: "memory");
    asm volatile("barrier.cluster.wait.aligned;" ::: "memory");
}
__device__ __forceinline__ void mbar_init(uint32_t a, uint32_t cnt) {
    asm volatile("mbarrier.init.shared.b64 [%0], %1;" :: "r"(a), "r"(cnt) : "memory");
}
__device__ __forceinline__ void mbar_expect_tx(uint32_t a, uint32_t bytes) {
    asm volatile("mbarrier.arrive.expect_tx.shared.b64 _, [%0], %1;"
                 :: "r"(a), "r"(bytes) : "memory");
}
__device__ __forceinline__ void mbar_wait(uint32_t a, uint32_t parity) {
    asm volatile(
        "{\n\t"
        ".reg .pred P1;\n"
        "LW_%=:\n\t"
        "mbarrier.try_wait.parity.acquire.cta.shared::cta.b64 P1, [%0], %1, 0x989680;\n\t"
        "@P1 bra LD_%=;\n\t"
        "bra LW_%=;\n"
        "LD_%=:\n\t"
        "}"
        :: "r"(a), "r"(parity) : "memory");
}
__device__ __forceinline__ uint32_t mapa_(uint32_t a, uint32_t pc) {
    uint32_t r;
    asm("mapa.shared::cluster.u32 %0, %1, %2;" : "=r"(r) : "r"(a), "r"(pc));
    return r;
}
__device__ __forceinline__ void st_async_tx(uint32_t raddr, float v, uint32_t rbar) {
    asm volatile("st.async.shared::cluster.mbarrier::complete_tx::bytes.b32 [%0], %1, [%2];"
                 :: "r"(raddr), "r"(__float_as_uint(v)), "r"(rbar) : "memory");
}
__device__ __forceinline__ void st_async_tx64(uint32_t raddr, unsigned long long v,
                                              uint32_t rbar) {
    asm volatile("st.async.shared::cluster.mbarrier::complete_tx::bytes.b64 [%0], %1, [%2];"
                 :: "r"(raddr), "l"(v), "r"(rbar) : "memory");
}
// fast, branch-free activations (__expf saturates cleanly at +-inf)
__device__ __forceinline__ float fsig(float x) {
    return __fdividef(1.0f, 1.0f + __expf(-x));
}
__device__ __forceinline__ float ftanh_(float x) {
    return 1.0f - __fdividef(2.0f, __expf(2.0f * x) + 1.0f);
}

// ---------------- kernel 1: embedding gather + input projection ----------------
__global__ __launch_bounds__(1024, 1)
void proj_kernel(const int* __restrict__ sent, const float* __restrict__ emb,
                 const float* __restrict__ Wf, const float* __restrict__ bihf,
                 const float* __restrict__ bhhf,
                 const float* __restrict__ Wb, const float* __restrict__ bihb,
                 const float* __restrict__ bhhb)
{
    __shared__ float4 xs[8][64];     // 8 timesteps x 256 floats
    const int dir = blockIdx.y;
    const int t0  = blockIdx.x * 8;
    const int tid = threadIdx.x;

    if (tid < 512) {
        int tt = tid >> 6, k4 = tid & 63;
        int s  = t0 + tt;
        int tok = sent[dir ? (LSEQ - 1 - s) : s];
        xs[tt][k4] = ((const float4*)emb)[(size_t)tok * 64 + k4];
    }
    __syncthreads();

    const float* W = dir ? Wb : Wf;
    const int row = tid;
    const float bias = dir ? (bihb[row] + bhhb[row]) : (bihf[row] + bhhf[row]);
    float acc[8];
#pragma unroll
    for (int i = 0; i < 8; i++) acc[i] = bias;

    const float4* W4 = (const float4*)(W + (size_t)row * DEMB);
#pragma unroll 8
    for (int k4 = 0; k4 < 64; k4++) {
        float4 w4 = __ldg(&W4[k4]);
#pragma unroll
        for (int tt = 0; tt < 8; tt++) {
            float4 x4 = xs[tt][k4];
            acc[tt] += w4.x * x4.x + w4.y * x4.y + w4.z * x4.z + w4.w * x4.w;
        }
    }
    float* out = g_xp[dir];
#pragma unroll
    for (int tt = 0; tt < 8; tt++)
        out[(size_t)(t0 + tt) * G4H + row] = acc[tt];
}

// ---------------- kernel 2: the sequential LSTM recurrence (R10 design) ----------------
// Grid: 16 CTAs, cluster of 8. Cluster 0 = forward, cluster 1 = backward.
// Each CTA owns h-slice [rank*32, rank*32+32); W_hh slice in registers as f32x2 pairs.
// h double-buffered in SMEM; remote fills via st.async + mbarrier complete_tx
// (1024 B per phase). Broadcast packed as b64 pairs: even lanes send
// (h_j, h_{j+1}) -> 128 tx-arrivals per barrier instead of 256, half the issue slots.
//
// RE-ARM ORDERING (proven in R10): full[p] is re-armed by tid0 IMMEDIATELY after
// its wait completes — before this CTA's __syncthreads, hence before any of this
// CTA's step-t st.async. A peer's step-(t+1) tx into our full[p] requires that
// peer to pass full[p^1] at t+1, which requires OUR step-t stores, which follow
// our __syncthreads, which tid0 only reaches after re-arming.
__global__ __launch_bounds__(512, 1) __cluster_dims__(8, 1, 1)
void lstm_kernel(const float* __restrict__ h0, const float* __restrict__ c0,
                 const float* __restrict__ Whh_f, const float* __restrict__ Whh_b)
{
    __shared__ __align__(16) float hb[2][HID];
    __shared__ float part[2][4][128];
    __shared__ __align__(8) unsigned long long mb_full[2];

    const int tid = threadIdx.x;
    uint32_t rank;
    asm("mov.u32 %0, %%cluster_ctarank;" : "=r"(rank));
    const int dir = blockIdx.x >> 3;

    const float* Whh = dir ? Whh_b : Whh_f;
    const float* xp  = g_xp[dir];

    const int lr = tid & 127;
    const int kq = tid >> 7;
    const int g  = lr >> 5;
    const int j  = lr & 31;
    const int grow = g * 256 + (int)rank * 32 + j;   // global gate row
    const int k0   = kq * 64;

    // W_hh slice as 32 packed f32x2 pairs (row is 1024B-aligned; k0*4 is 256B-aligned)
    unsigned long long w2[32];
    const unsigned long long* wrow =
        (const unsigned long long*)(Whh + (size_t)grow * HID + k0);
#pragma unroll
    for (int kk = 0; kk < 32; kk++) w2[kk] = __ldg(&wrow[kk]);

    const uint32_t fb0 = s2u(&mb_full[0]);
    const uint32_t fb1 = s2u(&mb_full[1]);

    // init + arm BEFORE cluster_sync so no tx can hit an un-armed barrier
    if (tid == 0) {
        mbar_init(fb0, 1);
        mbar_init(fb1, 1);
        mbar_expect_tx(fb0, 1024);   // phase 0: h0 fill
        mbar_expect_tx(fb1, 1024);   // phase 0: t=0 producer fill
    }
    __syncthreads();
    cluster_sync_();

    float c = 0.0f;
    float xpv[4] = {0.f, 0.f, 0.f, 0.f};
    if (tid < 32) {
        c = c0[dir * HID + rank * 32 + tid];
        float h0v = h0[dir * HID + rank * 32 + tid];
#pragma unroll
        for (int gg = 0; gg < 4; gg++)
            xpv[gg] = xp[gg * 256 + rank * 32 + tid];
        // h0 broadcast: b64 pairs from even lanes (tx -> full[0], 1024B total)
        float h0p = __shfl_down_sync(0xffffffffu, h0v, 1);
        if ((tid & 1) == 0) {
            unsigned long long pk =
                ((unsigned long long)__float_as_uint(h0p) << 32) | __float_as_uint(h0v);
            uint32_t lslot = s2u(&hb[0][rank * 32 + tid]);
#pragma unroll
            for (int pc = 0; pc < 8; pc++)
                st_async_tx64(mapa_(lslot, pc), pk, mapa_(fb0, pc));
        }
    }

    uint32_t phF0 = 0, phF1 = 0;
    int p = 0;
    for (int t = 0; t < LSEQ; t++) {
        // wait h(t) in hb[p], then re-arm the SAME barrier (safe: see note above)
        if (p == 0) {
            mbar_wait(fb0, phF0); phF0 ^= 1;
            if (tid == 0) mbar_expect_tx(fb0, 1024);
        } else {
            mbar_wait(fb1, phF1); phF1 ^= 1;
            if (tid == 0) mbar_expect_tx(fb1, 1024);
        }

        // prefetch next step's xp rows (hidden behind this step's dot compute)
        float xpn[4] = {0.f, 0.f, 0.f, 0.f};
        if (tid < 32 && t + 1 < LSEQ) {
#pragma unroll
            for (int gg = 0; gg < 4; gg++)
                xpn[gg] = __ldg(&xp[(size_t)(t + 1) * G4H + gg * 256 + rank * 32 + tid]);
        }

        // partial dot via packed f32x2 FMA (broadcast LDS.128, conflict-free)
        const ulonglong2* h8 = (const ulonglong2*)&hb[p][k0];
        unsigned long long a0 = 0ull, a1 = 0ull;
#pragma unroll
        for (int q = 0; q < 16; q++) {
            ulonglong2 hv = h8[q];
            asm("fma.rn.f32x2 %0, %1, %2, %0;" : "+l"(a0) : "l"(w2[2 * q]),     "l"(hv.x));
            asm("fma.rn.f32x2 %0, %1, %2, %0;" : "+l"(a1) : "l"(w2[2 * q + 1]), "l"(hv.y));
        }
        asm("add.rn.f32x2 %0, %1, %2;" : "=l"(a0) : "l"(a0), "l"(a1));
        uint32_t alo, ahi;
        asm("mov.b64 {%0,%1}, %2;" : "=r"(alo), "=r"(ahi) : "l"(a0));
        part[p][kq][lr] = __uint_as_float(alo) + __uint_as_float(ahi);
        __syncthreads();      // part[p] ready; all local reads of hb[p] retired

        if (tid < 32) {
            const int jj = tid;
            float gv[4];
#pragma unroll
            for (int gg = 0; gg < 4; gg++) {
                float s = part[p][0][gg * 32 + jj] + part[p][1][gg * 32 + jj]
                        + part[p][2][gg * 32 + jj] + part[p][3][gg * 32 + jj];
                gv[gg] = xpv[gg] + s;
            }
            float ii  = fsig(gv[0]);
            float ff  = fsig(gv[1]);
            float ggt = ftanh_(gv[2]);
            float oo  = fsig(gv[3]);
            c = ff * c + ii * ggt;
            float hj = oo * ftanh_(c);

            // emit to gmem in FINAL time order (backward direction un-reverses here)
            int tt = dir ? (LSEQ - 1 - t) : t;
            g_lstm_out[(size_t)tt * 512 + dir * 256 + rank * 32 + jj] = hj;

            if (t + 1 < LSEQ) {
                // b64-pair broadcast: even lanes send (own, partner)
                float hp = __shfl_down_sync(0xffffffffu, hj, 1);
                if ((jj & 1) == 0) {
                    unsigned long long pk =
                        ((unsigned long long)__float_as_uint(hp) << 32) | __float_as_uint(hj);
                    uint32_t lslot = s2u(&hb[p ^ 1][rank * 32 + jj]);
                    uint32_t fbn   = (p == 0) ? fb1 : fb0;
#pragma unroll
                    for (int pc = 0; pc < 8; pc++)
                        st_async_tx64(mapa_(lslot, pc), pk, mapa_(fbn, pc));
                }
            }
#pragma unroll
            for (int gg = 0; gg < 4; gg++) xpv[gg] = xpn[gg];
        }
        // no second __syncthreads: part is double-buffered by p; reuse of part[p]
        // at t+2 is ordered through two full-barrier generations.
        p ^= 1;
    }
}

// ---------------- kernel 3: feats = lstm_out @ W_out^T + b_out ----------------
__global__ __launch_bounds__(256, 4)
void feats_kernel(const float* __restrict__ Wout, const float* __restrict__ bout)
{
    int gw   = (blockIdx.x * blockDim.x + threadIdx.x) >> 5;
    int lane = threadIdx.x & 31;
    if (gw >= LSEQ * NT) return;
    int t = gw / NT, n = gw % NT;

    const float4* xr = (const float4*)(g_lstm_out + (size_t)t * 512);
    const float4* wr = (const float4*)(Wout + (size_t)n * 512);
    float acc = 0.0f;
#pragma unroll
    for (int q = 0; q < 4; q++) {
        float4 a = xr[q * 32 + lane];
        float4 b = __ldg(&wr[q * 32 + lane]);
        acc += a.x * b.x + a.y * b.y + a.z * b.z + a.w * b.w;
    }
#pragma unroll
    for (int off = 16; off; off >>= 1)
        acc += __shfl_down_sync(0xffffffffu, acc, off);
    if (lane == 0) g_feats[t * NT + n] = acc + bout[n];
}

// ---------------- kernel 4: Viterbi forward + backtrace ----------------
// Critical recurrence: shfl + add + 5-deep FMNMX tree + add (value only).
// Argmax recovered OFF the critical path via exact equality mask: m is one of
// the sc[k] values (pure fmaxf, no arithmetic), lowest set bit == jnp.argmax
// first-index semantics. bp kept in SMEM for an LDS backtrace.
#define BP_BYTES   (LSEQ * NT)               // 98304
#define FCH_BYTES  (256 * NT * 4)            // 24576
#define PATH_BYTES (LSEQ * 4)                // 16384
#define VSMEM      (BP_BYTES + FCH_BYTES + PATH_BYTES + 128)

__device__ __forceinline__ float vmax24_(const float* sc) {
    float v12[12];
#pragma unroll
    for (int m = 0; m < 12; m++) v12[m] = fmaxf(sc[2 * m], sc[2 * m + 1]);
    float v6[6];
#pragma unroll
    for (int m = 0; m < 6; m++) v6[m] = fmaxf(v12[2 * m], v12[2 * m + 1]);
    float v3[3];
#pragma unroll
    for (int m = 0; m < 3; m++) v3[m] = fmaxf(v6[2 * m], v6[2 * m + 1]);
    return fmaxf(fmaxf(v3[0], v3[1]), v3[2]);
}
__device__ __forceinline__ int argeq24_(const float* sc, float m) {
    unsigned msk = 0u;
#pragma unroll
    for (int k = 0; k < NT; k++) msk |= (sc[k] == m) ? (1u << k) : 0u;
    return __ffs(msk) - 1;
}

__global__ void viterbi_kernel(const float* __restrict__ trans,
                               float* __restrict__ out, int out_size)
{
    extern __shared__ char sm[];
    unsigned char* bp   = (unsigned char*)sm;
    float*         fch  = (float*)(sm + BP_BYTES);
    int*           path = (int*)(sm + BP_BYTES + FCH_BYTES);
    __shared__ float score_s;

    const int tid = threadIdx.x;

    float fvr = (tid == START_TAG) ? 0.0f : NEGINF;
    float trow[NT];
    if (tid < NT) {
#pragma unroll
        for (int p_ = 0; p_ < NT; p_++) trow[p_] = trans[tid * NT + p_];
    } else {
#pragma unroll
        for (int p_ = 0; p_ < NT; p_++) trow[p_] = 0.0f;
    }
    __syncthreads();

    for (int ch = 0; ch < LSEQ / 256; ch++) {
        const float* src = g_feats + (size_t)ch * 256 * NT;
        for (int i = tid; i < 256 * NT; i += blockDim.x) fch[i] = src[i];
        __syncthreads();

        if (tid < 32) {
            for (int s = 0; s < 256; s++) {
                int t = ch * 256 + s;
                float sc[NT];
#pragma unroll
                for (int k = 0; k < NT; k++)
                    sc[k] = __shfl_sync(0xffffffffu, fvr, k) + trow[k];

                float m = vmax24_(sc);                    // short critical chain
                float fval = (tid < NT) ? fch[s * NT + tid] : 0.0f;
                fvr = m + fval;                           // recurrence closed

                int bi = argeq24_(sc, m);                 // off critical path
                if (tid < NT) bp[t * NT + tid] = (unsigned char)bi;
            }
        }
        __syncthreads();
    }

    if (tid < 32) {
        float sc[NT];
#pragma unroll
        for (int k = 0; k < NT; k++)
            sc[k] = __shfl_sync(0xffffffffu, fvr, k) + __ldg(&trans[STOP_TAG * NT + k]);
        float m = vmax24_(sc);
        int bi = argeq24_(sc, m);

        if (tid == 0) {
            score_s = m;
            int tag = bi;
            for (int t = LSEQ - 1; t >= 0; t--) {
                path[t] = tag;
                tag = bp[t * NT + tag];
            }
        }
    }
    __syncthreads();

    // output: tuple (path_score, best_path) flattened as float32
    if (out_size >= LSEQ + 1) {
        if (tid == 0) out[0] = score_s;
        for (int t = tid; t < LSEQ; t += blockDim.x) out[1 + t] = (float)path[t];
    } else if (out_size >= LSEQ) {
        for (int t = tid; t < LSEQ; t += blockDim.x) out[t] = (float)path[t];
    } else if (out_size >= 1) {
        if (tid == 0) out[0] = score_s;
    }
}

// ---------------- launch ----------------
extern "C" void kernel_launch(void* const* d_in, const int* in_sizes, int n_in,
                              void* d_out, int out_size)
{
    const int*   sent  = (const int*)d_in[0];
    const float* h0    = (const float*)d_in[1];
    const float* c0    = (const float*)d_in[2];
    const float* emb   = (const float*)d_in[3];
    const float* Wihf  = (const float*)d_in[4];
    const float* Whhf  = (const float*)d_in[5];
    const float* bihf  = (const float*)d_in[6];
    const float* bhhf  = (const float*)d_in[7];
    const float* Wihb  = (const float*)d_in[8];
    const float* Whhb  = (const float*)d_in[9];
    const float* bihb  = (const float*)d_in[10];
    const float* bhhb  = (const float*)d_in[11];
    const float* Wout  = (const float*)d_in[12];
    const float* bout  = (const float*)d_in[13];
    const float* trans = (const float*)d_in[14];

    cudaFuncSetAttribute(viterbi_kernel,
                         cudaFuncAttributeMaxDynamicSharedMemorySize, VSMEM);

    proj_kernel<<<dim3(LSEQ / 8, 2), 1024>>>(sent, emb, Wihf, bihf, bhhf,
                                             Wihb, bihb, bhhb);
    lstm_kernel<<<16, 512>>>(h0, c0, Whhf, Whhb);

    int nwarps  = LSEQ * NT;
    int nblocks = (nwarps * 32 + 255) / 256;
    feats_kernel<<<nblocks, 256>>>(Wout, bout);

    viterbi_kernel<<<1, 128, VSMEM>>>(trans, (float*)d_out, out_size);
}

// round 14
// speedup vs baseline: 2.8185x; 1.0696x over previous
#include <cuda_runtime.h>
#include <cuda_bf16.h>
#include <cstdint>
#include <math.h>

// Problem constants
#define LSEQ   4096
#define DEMB   256
#define HID    256          // per-direction hidden
#define G4H    1024         // 4*HID
#define NT     24
#define START_TAG 22
#define STOP_TAG  23
#define NEGINF (-1.0e6f)

// ---------------- scratch (device globals; no allocation allowed) ----------------
__device__ float g_xp[2][LSEQ * G4H];      // input projections per direction (scan order)
__device__ float g_lstm_out[LSEQ * 512];   // [t][0:256)=fwd h, [256:512)=bwd h (final order)
__device__ float g_feats[LSEQ * NT];

// ---------------- helpers ----------------
__device__ __forceinline__ uint32_t s2u(const void* p) {
    return (uint32_t)__cvta_generic_to_shared(p);
}
__device__ __forceinline__ void cluster_sync_() {
    asm volatile("barrier.cluster.arrive.aligned;" ::: "memory");
    asm volatile("barrier.cluster.wait.aligned;" ::: "memory");
}
__device__ __forceinline__ void mbar_init(uint32_t a, uint32_t cnt) {
    asm volatile("mbarrier.init.shared.b64 [%0], %1;" :: "r"(a), "r"(cnt) : "memory");
}
__device__ __forceinline__ void mbar_expect_tx(uint32_t a, uint32_t bytes) {
    asm volatile("mbarrier.arrive.expect_tx.shared.b64 _, [%0], %1;"
                 :: "r"(a), "r"(bytes) : "memory");
}
__device__ __forceinline__ void mbar_wait(uint32_t a, uint32_t parity) {
    asm volatile(
        "{\n\t"
        ".reg .pred P1;\n"
        "LW_%=:\n\t"
        "mbarrier.try_wait.parity.acquire.cta.shared::cta.b64 P1, [%0], %1, 0x989680;\n\t"
        "@P1 bra LD_%=;\n\t"
        "bra LW_%=;\n"
        "LD_%=:\n\t"
        "}"
        :: "r"(a), "r"(parity) : "memory");
}
__device__ __forceinline__ uint32_t mapa_(uint32_t a, uint32_t pc) {
    uint32_t r;
    asm("mapa.shared::cluster.u32 %0, %1, %2;" : "=r"(r) : "r"(a), "r"(pc));
    return r;
}
__device__ __forceinline__ void st_async_tx(uint32_t raddr, float v, uint32_t rbar) {
    asm volatile("st.async.shared::cluster.mbarrier::complete_tx::bytes.b32 [%0], %1, [%2];"
                 :: "r"(raddr), "r"(__float_as_uint(v)), "r"(rbar) : "memory");
}
// fast, branch-free activations (__expf saturates cleanly at +-inf)
__device__ __forceinline__ float fsig(float x) {
    return __fdividef(1.0f, 1.0f + __expf(-x));
}
__device__ __forceinline__ float ftanh_(float x) {
    return 1.0f - __fdividef(2.0f, __expf(2.0f * x) + 1.0f);
}

// ---------------- kernel 1: embedding gather + input projection ----------------
__global__ __launch_bounds__(1024, 1)
void proj_kernel(const int* __restrict__ sent, const float* __restrict__ emb,
                 const float* __restrict__ Wf, const float* __restrict__ bihf,
                 const float* __restrict__ bhhf,
                 const float* __restrict__ Wb, const float* __restrict__ bihb,
                 const float* __restrict__ bhhb)
{
    __shared__ float4 xs[8][64];     // 8 timesteps x 256 floats
    const int dir = blockIdx.y;
    const int t0  = blockIdx.x * 8;
    const int tid = threadIdx.x;

    if (tid < 512) {
        int tt = tid >> 6, k4 = tid & 63;
        int s  = t0 + tt;
        int tok = sent[dir ? (LSEQ - 1 - s) : s];
        xs[tt][k4] = ((const float4*)emb)[(size_t)tok * 64 + k4];
    }
    __syncthreads();

    const float* W = dir ? Wb : Wf;
    const int row = tid;
    const float bias = dir ? (bihb[row] + bhhb[row]) : (bihf[row] + bhhf[row]);
    float acc[8];
#pragma unroll
    for (int i = 0; i < 8; i++) acc[i] = bias;

    const float4* W4 = (const float4*)(W + (size_t)row * DEMB);
#pragma unroll 8
    for (int k4 = 0; k4 < 64; k4++) {
        float4 w4 = __ldg(&W4[k4]);
#pragma unroll
        for (int tt = 0; tt < 8; tt++) {
            float4 x4 = xs[tt][k4];
            acc[tt] += w4.x * x4.x + w4.y * x4.y + w4.z * x4.z + w4.w * x4.w;
        }
    }
    float* out = g_xp[dir];
#pragma unroll
    for (int tt = 0; tt < 8; tt++)
        out[(size_t)(t0 + tt) * G4H + row] = acc[tt];
}

// ---------------- kernel 2: the sequential LSTM recurrence ----------------
// EXACT R10 transport (measured best): 256x fire-and-forget st.async.b32 from
// 32 lanes, double-buffered hb, 1024B expect_tx per phase, re-arm right after
// the wait. Local deltas vs R10:
//   * part transposed to [p][lr][kq] -> tail reads ONE LDS.128 per gate
//     (writers take a benign 4-way STS bank conflict)
//   * cross-CTA sends issued BEFORE the g_lstm_out STG (peers' critical path
//     starts at our sends; the gmem store is nobody's dependency)
//
// RE-ARM ORDERING (proven in R10): full[p] is re-armed by tid0 IMMEDIATELY after
// its wait completes — before this CTA's __syncthreads, hence before any of this
// CTA's step-t st.async. A peer's step-(t+1) tx into our full[p] requires that
// peer to pass full[p^1] at t+1, which requires OUR step-t stores, which follow
// our __syncthreads, which tid0 only reaches after re-arming.
__global__ __launch_bounds__(512, 1) __cluster_dims__(8, 1, 1)
void lstm_kernel(const float* __restrict__ h0, const float* __restrict__ c0,
                 const float* __restrict__ Whh_f, const float* __restrict__ Whh_b)
{
    __shared__ __align__(16) float hb[2][HID];
    __shared__ __align__(16) float part[2][128][4];
    __shared__ __align__(8) unsigned long long mb_full[2];

    const int tid = threadIdx.x;
    uint32_t rank;
    asm("mov.u32 %0, %%cluster_ctarank;" : "=r"(rank));
    const int dir = blockIdx.x >> 3;

    const float* Whh = dir ? Whh_b : Whh_f;
    const float* xp  = g_xp[dir];

    const int lr = tid & 127;
    const int kq = tid >> 7;
    const int g  = lr >> 5;
    const int j  = lr & 31;
    const int grow = g * 256 + (int)rank * 32 + j;   // global gate row
    const int k0   = kq * 64;

    // W_hh slice as 32 packed f32x2 pairs (row is 1024B-aligned; k0*4 is 256B-aligned)
    unsigned long long w2[32];
    const unsigned long long* wrow =
        (const unsigned long long*)(Whh + (size_t)grow * HID + k0);
#pragma unroll
    for (int kk = 0; kk < 32; kk++) w2[kk] = __ldg(&wrow[kk]);

    const uint32_t fb0 = s2u(&mb_full[0]);
    const uint32_t fb1 = s2u(&mb_full[1]);

    // init + arm BEFORE cluster_sync so no tx can hit an un-armed barrier
    if (tid == 0) {
        mbar_init(fb0, 1);
        mbar_init(fb1, 1);
        mbar_expect_tx(fb0, 1024);   // phase 0: h0 fill
        mbar_expect_tx(fb1, 1024);   // phase 0: t=0 producer fill
    }
    __syncthreads();
    cluster_sync_();

    float c = 0.0f;
    float xpv[4] = {0.f, 0.f, 0.f, 0.f};
    if (tid < 32) {
        c = c0[dir * HID + rank * 32 + tid];
        float h0v = h0[dir * HID + rank * 32 + tid];
#pragma unroll
        for (int gg = 0; gg < 4; gg++)
            xpv[gg] = xp[gg * 256 + rank * 32 + tid];
        // broadcast h0 slice to hb[0] of all 8 CTAs (incl self), tx -> full[0]
        uint32_t lslot = s2u(&hb[0][rank * 32 + tid]);
#pragma unroll
        for (int pc = 0; pc < 8; pc++)
            st_async_tx(mapa_(lslot, pc), h0v, mapa_(fb0, pc));
    }

    uint32_t phF0 = 0, phF1 = 0;
    int p = 0;
    for (int t = 0; t < LSEQ; t++) {
        // wait h(t) in hb[p], then re-arm the SAME barrier (safe: see note above)
        if (p == 0) {
            mbar_wait(fb0, phF0); phF0 ^= 1;
            if (tid == 0) mbar_expect_tx(fb0, 1024);
        } else {
            mbar_wait(fb1, phF1); phF1 ^= 1;
            if (tid == 0) mbar_expect_tx(fb1, 1024);
        }

        // prefetch next step's xp rows (hidden behind this step's dot compute)
        float xpn[4] = {0.f, 0.f, 0.f, 0.f};
        if (tid < 32 && t + 1 < LSEQ) {
#pragma unroll
            for (int gg = 0; gg < 4; gg++)
                xpn[gg] = __ldg(&xp[(size_t)(t + 1) * G4H + gg * 256 + rank * 32 + tid]);
        }

        // partial dot via packed f32x2 FMA (broadcast LDS.128, conflict-free)
        const ulonglong2* h8 = (const ulonglong2*)&hb[p][k0];
        unsigned long long a0 = 0ull, a1 = 0ull;
#pragma unroll
        for (int q = 0; q < 16; q++) {
            ulonglong2 hv = h8[q];
            asm("fma.rn.f32x2 %0, %1, %2, %0;" : "+l"(a0) : "l"(w2[2 * q]),     "l"(hv.x));
            asm("fma.rn.f32x2 %0, %1, %2, %0;" : "+l"(a1) : "l"(w2[2 * q + 1]), "l"(hv.y));
        }
        asm("add.rn.f32x2 %0, %1, %2;" : "=l"(a0) : "l"(a0), "l"(a1));
        uint32_t alo, ahi;
        asm("mov.b64 {%0,%1}, %2;" : "=r"(alo), "=r"(ahi) : "l"(a0));
        part[p][lr][kq] = __uint_as_float(alo) + __uint_as_float(ahi);
        __syncthreads();      // part[p] ready; all local reads of hb[p] retired

        if (tid < 32) {
            const int jj = tid;
            float gv[4];
#pragma unroll
            for (int gg = 0; gg < 4; gg++) {
                float4 pv = *(const float4*)&part[p][gg * 32 + jj][0];  // one LDS.128
                gv[gg] = xpv[gg] + ((pv.x + pv.y) + (pv.z + pv.w));
            }
            float ii  = fsig(gv[0]);
            float ff  = fsig(gv[1]);
            float ggt = ftanh_(gv[2]);
            float oo  = fsig(gv[3]);
            c = ff * c + ii * ggt;
            float hj = oo * ftanh_(c);

            // sends FIRST (peers' critical path), gmem store after
            if (t + 1 < LSEQ) {
                uint32_t lslot = s2u(&hb[p ^ 1][rank * 32 + jj]);
                uint32_t fbn   = (p == 0) ? fb1 : fb0;
#pragma unroll
                for (int pc = 0; pc < 8; pc++)
                    st_async_tx(mapa_(lslot, pc), hj, mapa_(fbn, pc));
            }

            // emit to gmem in FINAL time order (backward direction un-reverses here)
            int tt = dir ? (LSEQ - 1 - t) : t;
            g_lstm_out[(size_t)tt * 512 + dir * 256 + rank * 32 + jj] = hj;

#pragma unroll
            for (int gg = 0; gg < 4; gg++) xpv[gg] = xpn[gg];
        }
        // no second __syncthreads: part is double-buffered by p; reuse of part[p]
        // at t+2 is ordered through two full-barrier generations.
        p ^= 1;
    }
}

// ---------------- kernel 3: feats = lstm_out @ W_out^T + b_out ----------------
__global__ __launch_bounds__(256, 4)
void feats_kernel(const float* __restrict__ Wout, const float* __restrict__ bout)
{
    int gw   = (blockIdx.x * blockDim.x + threadIdx.x) >> 5;
    int lane = threadIdx.x & 31;
    if (gw >= LSEQ * NT) return;
    int t = gw / NT, n = gw % NT;

    const float4* xr = (const float4*)(g_lstm_out + (size_t)t * 512);
    const float4* wr = (const float4*)(Wout + (size_t)n * 512);
    float acc = 0.0f;
#pragma unroll
    for (int q = 0; q < 4; q++) {
        float4 a = xr[q * 32 + lane];
        float4 b = __ldg(&wr[q * 32 + lane]);
        acc += a.x * b.x + a.y * b.y + a.z * b.z + a.w * b.w;
    }
#pragma unroll
    for (int off = 16; off; off >>= 1)
        acc += __shfl_down_sync(0xffffffffu, acc, off);
    if (lane == 0) g_feats[t * NT + n] = acc + bout[n];
}

// ---------------- kernel 4: Viterbi forward + backtrace ----------------
// Critical recurrence: shfl + add + 5-deep FMNMX tree + add (value only).
// Argmax recovered OFF the critical path via exact equality mask: m is one of
// the sc[k] values (pure fmaxf, no arithmetic), lowest set bit == jnp.argmax
// first-index semantics. bp kept in SMEM for an LDS backtrace.
#define BP_BYTES   (LSEQ * NT)               // 98304
#define FCH_BYTES  (256 * NT * 4)            // 24576
#define PATH_BYTES (LSEQ * 4)                // 16384
#define VSMEM      (BP_BYTES + FCH_BYTES + PATH_BYTES + 128)

__device__ __forceinline__ float vmax24_(const float* sc) {
    float v12[12];
#pragma unroll
    for (int m = 0; m < 12; m++) v12[m] = fmaxf(sc[2 * m], sc[2 * m + 1]);
    float v6[6];
#pragma unroll
    for (int m = 0; m < 6; m++) v6[m] = fmaxf(v12[2 * m], v12[2 * m + 1]);
    float v3[3];
#pragma unroll
    for (int m = 0; m < 3; m++) v3[m] = fmaxf(v6[2 * m], v6[2 * m + 1]);
    return fmaxf(fmaxf(v3[0], v3[1]), v3[2]);
}
__device__ __forceinline__ int argeq24_(const float* sc, float m) {
    unsigned msk = 0u;
#pragma unroll
    for (int k = 0; k < NT; k++) msk |= (sc[k] == m) ? (1u << k) : 0u;
    return __ffs(msk) - 1;
}

__global__ void viterbi_kernel(const float* __restrict__ trans,
                               float* __restrict__ out, int out_size)
{
    extern __shared__ char sm[];
    unsigned char* bp   = (unsigned char*)sm;
    float*         fch  = (float*)(sm + BP_BYTES);
    int*           path = (int*)(sm + BP_BYTES + FCH_BYTES);
    __shared__ float score_s;

    const int tid = threadIdx.x;

    float fvr = (tid == START_TAG) ? 0.0f : NEGINF;
    float trow[NT];
    if (tid < NT) {
#pragma unroll
        for (int p_ = 0; p_ < NT; p_++) trow[p_] = trans[tid * NT + p_];
    } else {
#pragma unroll
        for (int p_ = 0; p_ < NT; p_++) trow[p_] = 0.0f;
    }
    __syncthreads();

    for (int ch = 0; ch < LSEQ / 256; ch++) {
        const float* src = g_feats + (size_t)ch * 256 * NT;
        for (int i = tid; i < 256 * NT; i += blockDim.x) fch[i] = src[i];
        __syncthreads();

        if (tid < 32) {
            for (int s = 0; s < 256; s++) {
                int t = ch * 256 + s;
                float sc[NT];
#pragma unroll
                for (int k = 0; k < NT; k++)
                    sc[k] = __shfl_sync(0xffffffffu, fvr, k) + trow[k];

                float m = vmax24_(sc);                    // short critical chain
                float fval = (tid < NT) ? fch[s * NT + tid] : 0.0f;
                fvr = m + fval;                           // recurrence closed

                int bi = argeq24_(sc, m);                 // off critical path
                if (tid < NT) bp[t * NT + tid] = (unsigned char)bi;
            }
        }
        __syncthreads();
    }

    if (tid < 32) {
        float sc[NT];
#pragma unroll
        for (int k = 0; k < NT; k++)
            sc[k] = __shfl_sync(0xffffffffu, fvr, k) + __ldg(&trans[STOP_TAG * NT + k]);
        float m = vmax24_(sc);
        int bi = argeq24_(sc, m);

        if (tid == 0) {
            score_s = m;
            int tag = bi;
            for (int t = LSEQ - 1; t >= 0; t--) {
                path[t] = tag;
                tag = bp[t * NT + tag];
            }
        }
    }
    __syncthreads();

    // output: tuple (path_score, best_path) flattened as float32
    if (out_size >= LSEQ + 1) {
        if (tid == 0) out[0] = score_s;
        for (int t = tid; t < LSEQ; t += blockDim.x) out[1 + t] = (float)path[t];
    } else if (out_size >= LSEQ) {
        for (int t = tid; t < LSEQ; t += blockDim.x) out[t] = (float)path[t];
    } else if (out_size >= 1) {
        if (tid == 0) out[0] = score_s;
    }
}

// ---------------- launch ----------------
extern "C" void kernel_launch(void* const* d_in, const int* in_sizes, int n_in,
                              void* d_out, int out_size)
{
    const int*   sent  = (const int*)d_in[0];
    const float* h0    = (const float*)d_in[1];
    const float* c0    = (const float*)d_in[2];
    const float* emb   = (const float*)d_in[3];
    const float* Wihf  = (const float*)d_in[4];
    const float* Whhf  = (const float*)d_in[5];
    const float* bihf  = (const float*)d_in[6];
    const float* bhhf  = (const float*)d_in[7];
    const float* Wihb  = (const float*)d_in[8];
    const float* Whhb  = (const float*)d_in[9];
    const float* bihb  = (const float*)d_in[10];
    const float* bhhb  = (const float*)d_in[11];
    const float* Wout  = (const float*)d_in[12];
    const float* bout  = (const float*)d_in[13];
    const float* trans = (const float*)d_in[14];

    cudaFuncSetAttribute(viterbi_kernel,
                         cudaFuncAttributeMaxDynamicSharedMemorySize, VSMEM);

    proj_kernel<<<dim3(LSEQ / 8, 2), 1024>>>(sent, emb, Wihf, bihf, bhhf,
                                             Wihb, bihb, bhhb);
    lstm_kernel<<<16, 512>>>(h0, c0, Whhf, Whhb);

    int nwarps  = LSEQ * NT;
    int nblocks = (nwarps * 32 + 255) / 256;
    feats_kernel<<<nblocks, 256>>>(Wout, bout);

    viterbi_kernel<<<1, 128, VSMEM>>>(trans, (float*)d_out, out_size);
}